// round 1
// baseline (speedup 1.0000x reference)
#include <cuda_runtime.h>
#include <cstdint>

#define MAX_NODES 100000
#define UNITS 128

// Scratch (no cudaMalloc allowed)
__device__ float g_h[(size_t)MAX_NODES * UNITS];   // 51.2 MB: h = X @ W
__device__ int   g_row_ptr[MAX_NODES + 1];
__device__ int   g_idx64;                          // 1 if edge indices are int64

// ---------------------------------------------------------------------------
// Index-dtype probe: edge_col is uniform random in [0, 1e5). If the buffer is
// int64, every odd int32 word (high half) of the first 32 elements is zero.
// If int32, the odd words are random values — P(all 32 == 0) ~ 1e-160.
// Deterministic: same input -> same flag every launch.
// ---------------------------------------------------------------------------
__global__ void detect_kernel(const int* __restrict__ ec) {
    if (threadIdx.x == 0 && blockIdx.x == 0) {
        int nz = 0;
        #pragma unroll
        for (int i = 1; i < 64; i += 2) nz += (ec[i] != 0);
        g_idx64 = (nz == 0) ? 1 : 0;
    }
}

__device__ __forceinline__ int load_idx(const void* p, int i, int is64) {
    if (is64) return (int)__ldg(((const long long*)p) + i);
    return __ldg(((const int*)p) + i);
}

// ---------------------------------------------------------------------------
// CSR row_ptr from sorted edge_row via lower_bound binary search.
// row_ptr[node] = first edge index with edge_row >= node; row_ptr[M] = E.
// ---------------------------------------------------------------------------
__global__ void rowptr_kernel(const void* __restrict__ er, int E, int M) {
    int node = blockIdx.x * blockDim.x + threadIdx.x;
    if (node > M) return;
    int is64 = g_idx64;
    int lo = 0, hi = E;
    while (lo < hi) {
        int mid = (lo + hi) >> 1;
        if (load_idx(er, mid, is64) < node) lo = mid + 1; else hi = mid;
    }
    g_row_ptr[node] = lo;
}

// ---------------------------------------------------------------------------
// GEMM: g_h[M,128] = X[M,128] @ W[128,128], fp32.
// Block tile 64(M) x 128(N), K tiled by 32. 256 threads, each computes a
// 4x8 register micro-tile (3 LDS.128 feed 32 FFMA per k-step).
// Xs stored K-major-transposed so the 4 A values per thread are one float4.
// ---------------------------------------------------------------------------
__global__ __launch_bounds__(256) void gemm_kernel(
    const float* __restrict__ X, const float* __restrict__ W, int M)
{
    __shared__ float Xs[32][64];    // [k][m]
    __shared__ float Ws[32][128];   // [k][n]

    int tid = threadIdx.x;
    int tx = tid & 15;              // 0..15 -> 8 output cols each
    int ty = tid >> 4;              // 0..15 -> 4 output rows each
    int m0 = blockIdx.x * 64;

    float acc[4][8];
    #pragma unroll
    for (int i = 0; i < 4; i++)
        #pragma unroll
        for (int j = 0; j < 8; j++) acc[i][j] = 0.0f;

    for (int k0 = 0; k0 < 128; k0 += 32) {
        // --- load X tile (64 rows x 32 k) transposed into Xs[k][m] ---
        {
            int row = tid >> 2;          // 0..63
            int kq  = (tid & 3) * 8;     // 0,8,16,24
            float4 v0 = {0,0,0,0}, v1 = {0,0,0,0};
            if (m0 + row < M) {
                const float4* src = (const float4*)(X + (size_t)(m0 + row) * 128 + k0 + kq);
                v0 = __ldg(src);
                v1 = __ldg(src + 1);
            }
            Xs[kq+0][row] = v0.x; Xs[kq+1][row] = v0.y;
            Xs[kq+2][row] = v0.z; Xs[kq+3][row] = v0.w;
            Xs[kq+4][row] = v1.x; Xs[kq+5][row] = v1.y;
            Xs[kq+6][row] = v1.z; Xs[kq+7][row] = v1.w;
        }
        // --- load W tile (32 k x 128 n), coalesced float4 ---
        #pragma unroll
        for (int j = 0; j < 4; j++) {
            int idx = tid + j * 256;     // float4 index 0..1023
            int kk = idx >> 5;           // 32 float4 per row
            int nn = (idx & 31) << 2;
            *(float4*)&Ws[kk][nn] =
                __ldg((const float4*)(W + (size_t)(k0 + kk) * 128 + nn));
        }
        __syncthreads();

        #pragma unroll 8
        for (int kk = 0; kk < 32; kk++) {
            float4 a  = *(const float4*)&Xs[kk][ty * 4];
            float4 b0 = *(const float4*)&Ws[kk][tx * 8];
            float4 b1 = *(const float4*)&Ws[kk][tx * 8 + 4];
            float av[4] = {a.x, a.y, a.z, a.w};
            float bv[8] = {b0.x, b0.y, b0.z, b0.w, b1.x, b1.y, b1.z, b1.w};
            #pragma unroll
            for (int i = 0; i < 4; i++)
                #pragma unroll
                for (int j = 0; j < 8; j++)
                    acc[i][j] += av[i] * bv[j];
        }
        __syncthreads();
    }

    #pragma unroll
    for (int i = 0; i < 4; i++) {
        int m = m0 + ty * 4 + i;
        if (m < M) {
            float4 o0 = {acc[i][0], acc[i][1], acc[i][2], acc[i][3]};
            float4 o1 = {acc[i][4], acc[i][5], acc[i][6], acc[i][7]};
            float* dst = g_h + (size_t)m * 128 + tx * 8;
            *(float4*)(dst)     = o0;
            *(float4*)(dst + 4) = o1;
        }
    }
}

// ---------------------------------------------------------------------------
// SpMM + bias + sigmoid, one block (128 threads) per row, no atomics.
// 4-edge software pipeline gives MLP=4 on the h[col] gathers.
// Rows with zero edges correctly emit sigmoid(bias) — matches segment_sum.
// ---------------------------------------------------------------------------
__global__ __launch_bounds__(128) void spmm_kernel(
    const void* __restrict__ ec, const float* __restrict__ ev,
    const float* __restrict__ bias, float* __restrict__ out)
{
    int r = blockIdx.x;
    int t = threadIdx.x;
    int is64 = g_idx64;
    int s = g_row_ptr[r];
    int e = g_row_ptr[r + 1];

    float acc = 0.0f;
    int i = s;
    for (; i + 4 <= e; i += 4) {
        int c0 = load_idx(ec, i + 0, is64);
        int c1 = load_idx(ec, i + 1, is64);
        int c2 = load_idx(ec, i + 2, is64);
        int c3 = load_idx(ec, i + 3, is64);
        float v0 = __ldg(ev + i + 0);
        float v1 = __ldg(ev + i + 1);
        float v2 = __ldg(ev + i + 2);
        float v3 = __ldg(ev + i + 3);
        float h0 = g_h[(size_t)c0 * UNITS + t];
        float h1 = g_h[(size_t)c1 * UNITS + t];
        float h2 = g_h[(size_t)c2 * UNITS + t];
        float h3 = g_h[(size_t)c3 * UNITS + t];
        acc += v0 * h0;
        acc += v1 * h1;
        acc += v2 * h2;
        acc += v3 * h3;
    }
    for (; i < e; i++) {
        int c = load_idx(ec, i, is64);
        acc += __ldg(ev + i) * g_h[(size_t)c * UNITS + t];
    }

    float x = acc + __ldg(bias + t);
    out[(size_t)r * UNITS + t] = 1.0f / (1.0f + __expf(-x));
}

// ---------------------------------------------------------------------------
// Launch. Inputs (metadata order): X, edge_row, edge_col, edge_val, weight, bias
// ---------------------------------------------------------------------------
extern "C" void kernel_launch(void* const* d_in, const int* in_sizes, int n_in,
                              void* d_out, int out_size) {
    const float* X    = (const float*)d_in[0];
    const void*  er   = d_in[1];
    const void*  ec   = d_in[2];
    const float* ev   = (const float*)d_in[3];
    const float* W    = (const float*)d_in[4];
    const float* bias = (const float*)d_in[5];
    float* out = (float*)d_out;

    int M = in_sizes[0] / UNITS;     // 100000
    int E = in_sizes[2];             // 1600000

    detect_kernel<<<1, 32>>>((const int*)ec);
    gemm_kernel<<<(M + 63) / 64, 256>>>(X, W, M);
    rowptr_kernel<<<(M + 256) / 256, 256>>>(er, E, M);
    spmm_kernel<<<M, 128>>>(ec, ev, bias, out);
}

// round 3
// speedup vs baseline: 1.4108x; 1.4108x over previous
#include <cuda_runtime.h>
#include <cstdint>

#define MAX_NODES 100000
#define UNITS 128

// Scratch (no cudaMalloc allowed)
__device__ float g_h[(size_t)MAX_NODES * UNITS];   // 51.2 MB: h = X @ W
__device__ int   g_row_ptr[MAX_NODES + 1];
__device__ int   g_idx64;                          // 1 if edge indices are int64

// ---------------------------------------------------------------------------
// Index-dtype probe: edge_col is uniform random in [0, 1e5). If the buffer is
// int64, every odd int32 word (high half) of the first 32 elements is zero.
// If int32, odd words are random values — P(all 32 == 0) ~ 1e-160.
// ---------------------------------------------------------------------------
__global__ void detect_kernel(const int* __restrict__ ec) {
    if (threadIdx.x == 0 && blockIdx.x == 0) {
        int nz = 0;
        #pragma unroll
        for (int i = 1; i < 64; i += 2) nz += (ec[i] != 0);
        g_idx64 = (nz == 0) ? 1 : 0;
    }
}

template <int IS64>
__device__ __forceinline__ int load_idx(const void* p, int i) {
    if (IS64) return (int)__ldg(((const long long*)p) + i);
    return __ldg(((const int*)p) + i);
}

// ---------------------------------------------------------------------------
// CSR row_ptr from sorted edge_row via lower_bound binary search.
// ---------------------------------------------------------------------------
template <int IS64>
__global__ void rowptr_kernel(const void* __restrict__ er, int E, int M) {
    int node = blockIdx.x * blockDim.x + threadIdx.x;
    if (node > M) return;
    int lo = 0, hi = E;
    while (lo < hi) {
        int mid = (lo + hi) >> 1;
        if (load_idx<IS64>(er, mid) < node) lo = mid + 1; else hi = mid;
    }
    g_row_ptr[node] = lo;
}

__global__ void rowptr_dispatch_is_on_host_note() {}  // (unused)

// ---------------------------------------------------------------------------
// GEMM: g_h[M,128] = X[M,128] @ W[128,128], fp32.
// 128(M) x 128(N) block tile, K tiled by 16, double-buffered smem,
// 256 threads, 8x8 register micro-tile (4 LDS.128 feed 64 FFMA per k-step).
// Xs stored transposed [k][m] so A-fragments are contiguous float4s.
// ---------------------------------------------------------------------------
#define KT 16
#define XS_STRIDE 132

__global__ __launch_bounds__(256) void gemm_kernel(
    const float* __restrict__ X, const float* __restrict__ W, int M)
{
    __shared__ float Xs[2][KT][XS_STRIDE];
    __shared__ float Ws[2][KT][128];

    int tid = threadIdx.x;
    int m0 = blockIdx.x * 128;
    int tx = (tid & 15) * 8;     // output col base (8 cols)
    int ty = (tid >> 4) * 8;     // output row base (8 rows)

    // X loader: each thread loads 8 floats of one row (2 float4)
    int xr = tid >> 1;           // 0..127 row within tile
    int xk = (tid & 1) * 8;      // 0 or 8
    bool xv = (m0 + xr) < M;
    const float* xbase = X + (size_t)(m0 + xr) * 128 + xk;

    // W loader: 16x128 tile = 512 float4; each thread loads 2 consecutive
    int widx = tid * 2;
    int wk = widx >> 5;          // both float4 in same k-row (widx even)
    int wn = (widx & 31) * 4;
    const float* wbase = W + (size_t)wk * 128 + wn;

    float acc[8][8];
    #pragma unroll
    for (int i = 0; i < 8; i++)
        #pragma unroll
        for (int j = 0; j < 8; j++) acc[i][j] = 0.0f;

    // prefetch registers
    float4 px0, px1, pw0, pw1;

    // --- load tile 0 ---
    px0 = make_float4(0,0,0,0); px1 = px0;
    if (xv) { px0 = __ldg((const float4*)xbase); px1 = __ldg((const float4*)(xbase + 4)); }
    pw0 = __ldg((const float4*)wbase);
    pw1 = __ldg((const float4*)(wbase + 4));
    {
        Xs[0][xk+0][xr] = px0.x; Xs[0][xk+1][xr] = px0.y;
        Xs[0][xk+2][xr] = px0.z; Xs[0][xk+3][xr] = px0.w;
        Xs[0][xk+4][xr] = px1.x; Xs[0][xk+5][xr] = px1.y;
        Xs[0][xk+6][xr] = px1.z; Xs[0][xk+7][xr] = px1.w;
        *(float4*)&Ws[0][wk][wn]     = pw0;
        *(float4*)&Ws[0][wk][wn + 4] = pw1;
    }
    __syncthreads();

    #pragma unroll 1
    for (int t = 0; t < 8; t++) {
        int cur = t & 1;
        // issue global loads for next tile (latency hidden by compute)
        if (t < 7) {
            int k0 = (t + 1) * KT;
            px0 = make_float4(0,0,0,0); px1 = px0;
            if (xv) {
                px0 = __ldg((const float4*)(xbase + k0));
                px1 = __ldg((const float4*)(xbase + k0 + 4));
            }
            pw0 = __ldg((const float4*)(wbase + (size_t)k0 * 128));
            pw1 = __ldg((const float4*)(wbase + (size_t)k0 * 128 + 4));
        }

        #pragma unroll
        for (int kk = 0; kk < KT; kk++) {
            float4 a0 = *(const float4*)&Xs[cur][kk][ty];
            float4 a1 = *(const float4*)&Xs[cur][kk][ty + 4];
            float4 b0 = *(const float4*)&Ws[cur][kk][tx];
            float4 b1 = *(const float4*)&Ws[cur][kk][tx + 4];
            float av[8] = {a0.x, a0.y, a0.z, a0.w, a1.x, a1.y, a1.z, a1.w};
            float bv[8] = {b0.x, b0.y, b0.z, b0.w, b1.x, b1.y, b1.z, b1.w};
            #pragma unroll
            for (int i = 0; i < 8; i++)
                #pragma unroll
                for (int j = 0; j < 8; j++)
                    acc[i][j] = fmaf(av[i], bv[j], acc[i][j]);
        }

        if (t < 7) {
            int nxt = cur ^ 1;
            Xs[nxt][xk+0][xr] = px0.x; Xs[nxt][xk+1][xr] = px0.y;
            Xs[nxt][xk+2][xr] = px0.z; Xs[nxt][xk+3][xr] = px0.w;
            Xs[nxt][xk+4][xr] = px1.x; Xs[nxt][xk+5][xr] = px1.y;
            Xs[nxt][xk+6][xr] = px1.z; Xs[nxt][xk+7][xr] = px1.w;
            *(float4*)&Ws[nxt][wk][wn]     = pw0;
            *(float4*)&Ws[nxt][wk][wn + 4] = pw1;
            __syncthreads();
        }
    }

    // epilogue
    #pragma unroll
    for (int i = 0; i < 8; i++) {
        int m = m0 + ty + i;
        if (m < M) {
            float* dst = g_h + (size_t)m * 128 + tx;
            *(float4*)(dst)     = make_float4(acc[i][0], acc[i][1], acc[i][2], acc[i][3]);
            *(float4*)(dst + 4) = make_float4(acc[i][4], acc[i][5], acc[i][6], acc[i][7]);
        }
    }
}

// ---------------------------------------------------------------------------
// SpMM + bias + sigmoid. ONE WARP per row; each lane owns a float4 column
// slice, so h[col] is gathered with a single LDG.128 warp-instruction per
// edge. 4-edge unroll gives MLP=4. No atomics (rows are CSR segments).
// ---------------------------------------------------------------------------
template <int IS64>
__global__ __launch_bounds__(256) void spmm_kernel(
    const void* __restrict__ ec, const float* __restrict__ ev,
    const float* __restrict__ bias, float* __restrict__ out, int M)
{
    int row = blockIdx.x * 8 + (threadIdx.x >> 5);
    if (row >= M) return;
    int lane = threadIdx.x & 31;

    int s = g_row_ptr[row];
    int e = g_row_ptr[row + 1];

    const float4* hp = (const float4*)g_h;
    float4 acc = make_float4(0, 0, 0, 0);

    int i = s;
    for (; i + 4 <= e; i += 4) {
        int c0 = load_idx<IS64>(ec, i + 0);
        int c1 = load_idx<IS64>(ec, i + 1);
        int c2 = load_idx<IS64>(ec, i + 2);
        int c3 = load_idx<IS64>(ec, i + 3);
        float v0 = __ldg(ev + i + 0);
        float v1 = __ldg(ev + i + 1);
        float v2 = __ldg(ev + i + 2);
        float v3 = __ldg(ev + i + 3);
        float4 h0 = hp[(size_t)c0 * 32 + lane];
        float4 h1 = hp[(size_t)c1 * 32 + lane];
        float4 h2 = hp[(size_t)c2 * 32 + lane];
        float4 h3 = hp[(size_t)c3 * 32 + lane];
        acc.x = fmaf(v0, h0.x, acc.x); acc.y = fmaf(v0, h0.y, acc.y);
        acc.z = fmaf(v0, h0.z, acc.z); acc.w = fmaf(v0, h0.w, acc.w);
        acc.x = fmaf(v1, h1.x, acc.x); acc.y = fmaf(v1, h1.y, acc.y);
        acc.z = fmaf(v1, h1.z, acc.z); acc.w = fmaf(v1, h1.w, acc.w);
        acc.x = fmaf(v2, h2.x, acc.x); acc.y = fmaf(v2, h2.y, acc.y);
        acc.z = fmaf(v2, h2.z, acc.z); acc.w = fmaf(v2, h2.w, acc.w);
        acc.x = fmaf(v3, h3.x, acc.x); acc.y = fmaf(v3, h3.y, acc.y);
        acc.z = fmaf(v3, h3.z, acc.z); acc.w = fmaf(v3, h3.w, acc.w);
    }
    for (; i < e; i++) {
        int c = load_idx<IS64>(ec, i);
        float v = __ldg(ev + i);
        float4 h = hp[(size_t)c * 32 + lane];
        acc.x = fmaf(v, h.x, acc.x); acc.y = fmaf(v, h.y, acc.y);
        acc.z = fmaf(v, h.z, acc.z); acc.w = fmaf(v, h.w, acc.w);
    }

    float4 b = __ldg(((const float4*)bias) + lane);
    float4 r;
    r.x = 1.0f / (1.0f + __expf(-(acc.x + b.x)));
    r.y = 1.0f / (1.0f + __expf(-(acc.y + b.y)));
    r.z = 1.0f / (1.0f + __expf(-(acc.z + b.z)));
    r.w = 1.0f / (1.0f + __expf(-(acc.w + b.w)));
    ((float4*)out)[(size_t)row * 32 + lane] = r;
}

// ---------------------------------------------------------------------------
// Dispatcher: reads g_idx64 on device and launches nothing — instead we
// launch BOTH template variants guarded by a device-side early-out?  No —
// cheaper: a tiny kernel copies g_idx64 into both template kernels' guard.
// Simplest correct scheme: launch both variants; the wrong one exits
// immediately via a guard on g_idx64.
// ---------------------------------------------------------------------------
template <int IS64>
__global__ void rowptr_guarded(const void* __restrict__ er, int E, int M) {
    if (g_idx64 != IS64) return;
    int node = blockIdx.x * blockDim.x + threadIdx.x;
    if (node > M) return;
    int lo = 0, hi = E;
    while (lo < hi) {
        int mid = (lo + hi) >> 1;
        if (load_idx<IS64>(er, mid) < node) lo = mid + 1; else hi = mid;
    }
    g_row_ptr[node] = lo;
}

template <int IS64>
__global__ __launch_bounds__(256) void spmm_guarded(
    const void* __restrict__ ec, const float* __restrict__ ev,
    const float* __restrict__ bias, float* __restrict__ out, int M)
{
    if (g_idx64 != IS64) return;
    int row = blockIdx.x * 8 + (threadIdx.x >> 5);
    if (row >= M) return;
    int lane = threadIdx.x & 31;

    int s = g_row_ptr[row];
    int e = g_row_ptr[row + 1];

    const float4* hp = (const float4*)g_h;
    float4 acc = make_float4(0, 0, 0, 0);

    int i = s;
    for (; i + 4 <= e; i += 4) {
        int c0 = load_idx<IS64>(ec, i + 0);
        int c1 = load_idx<IS64>(ec, i + 1);
        int c2 = load_idx<IS64>(ec, i + 2);
        int c3 = load_idx<IS64>(ec, i + 3);
        float v0 = __ldg(ev + i + 0);
        float v1 = __ldg(ev + i + 1);
        float v2 = __ldg(ev + i + 2);
        float v3 = __ldg(ev + i + 3);
        float4 h0 = hp[(size_t)c0 * 32 + lane];
        float4 h1 = hp[(size_t)c1 * 32 + lane];
        float4 h2 = hp[(size_t)c2 * 32 + lane];
        float4 h3 = hp[(size_t)c3 * 32 + lane];
        acc.x = fmaf(v0, h0.x, acc.x); acc.y = fmaf(v0, h0.y, acc.y);
        acc.z = fmaf(v0, h0.z, acc.z); acc.w = fmaf(v0, h0.w, acc.w);
        acc.x = fmaf(v1, h1.x, acc.x); acc.y = fmaf(v1, h1.y, acc.y);
        acc.z = fmaf(v1, h1.z, acc.z); acc.w = fmaf(v1, h1.w, acc.w);
        acc.x = fmaf(v2, h2.x, acc.x); acc.y = fmaf(v2, h2.y, acc.y);
        acc.z = fmaf(v2, h2.z, acc.z); acc.w = fmaf(v2, h2.w, acc.w);
        acc.x = fmaf(v3, h3.x, acc.x); acc.y = fmaf(v3, h3.y, acc.y);
        acc.z = fmaf(v3, h3.z, acc.z); acc.w = fmaf(v3, h3.w, acc.w);
    }
    for (; i < e; i++) {
        int c = load_idx<IS64>(ec, i);
        float v = __ldg(ev + i);
        float4 h = hp[(size_t)c * 32 + lane];
        acc.x = fmaf(v, h.x, acc.x); acc.y = fmaf(v, h.y, acc.y);
        acc.z = fmaf(v, h.z, acc.z); acc.w = fmaf(v, h.w, acc.w);
    }

    float4 b = __ldg(((const float4*)bias) + lane);
    float4 r;
    r.x = 1.0f / (1.0f + __expf(-(acc.x + b.x)));
    r.y = 1.0f / (1.0f + __expf(-(acc.y + b.y)));
    r.z = 1.0f / (1.0f + __expf(-(acc.z + b.z)));
    r.w = 1.0f / (1.0f + __expf(-(acc.w + b.w)));
    ((float4*)out)[(size_t)row * 32 + lane] = r;
}

// ---------------------------------------------------------------------------
// Launch. Inputs (metadata order): X, edge_row, edge_col, edge_val, weight, bias
// ---------------------------------------------------------------------------
extern "C" void kernel_launch(void* const* d_in, const int* in_sizes, int n_in,
                              void* d_out, int out_size) {
    const float* X    = (const float*)d_in[0];
    const void*  er   = d_in[1];
    const void*  ec   = d_in[2];
    const float* ev   = (const float*)d_in[3];
    const float* W    = (const float*)d_in[4];
    const float* bias = (const float*)d_in[5];
    float* out = (float*)d_out;

    int M = in_sizes[0] / UNITS;     // 100000
    int E = in_sizes[2];             // 1600000

    detect_kernel<<<1, 32>>>((const int*)ec);

    gemm_kernel<<<(M + 127) / 128, 256>>>(X, W, M);

    // both variants launched; the wrong-dtype one exits at block start
    rowptr_guarded<0><<<(M + 256) / 256, 256>>>(er, E, M);
    rowptr_guarded<1><<<(M + 256) / 256, 256>>>(er, E, M);

    int spmm_blocks = (M + 7) / 8;
    spmm_guarded<0><<<spmm_blocks, 256>>>(ec, ev, bias, out, M);
    spmm_guarded<1><<<spmm_blocks, 256>>>(ec, ev, bias, out, M);
}

// round 6
// speedup vs baseline: 2.7738x; 1.9660x over previous
#include <cuda_runtime.h>
#include <cuda_bf16.h>
#include <cstdint>

#define MAX_NODES 100000
#define UNITS 128

// ---------------------------------------------------------------------------
// Scratch (no cudaMalloc allowed)
// ---------------------------------------------------------------------------
__device__ __align__(16) float g_h[(size_t)MAX_NODES * UNITS];  // 51.2 MB
__device__ int   g_row_ptr[MAX_NODES + 1];
__device__ int   g_idx64;
// W split into bf16 hi/lo, stored as B[n][k] = W[k][n], row-major [128][128]
__device__ __align__(16) unsigned short g_whi[128 * 128];
__device__ __align__(16) unsigned short g_wlo[128 * 128];

__device__ __forceinline__ uint32_t smem_u32(const void* p) {
    uint32_t a;
    asm("{ .reg .u64 t; cvta.to.shared.u64 t, %1; cvt.u32.u64 %0, t; }"
        : "=r"(a) : "l"(p));
    return a;
}

// ---------------------------------------------------------------------------
// Index-dtype probe (int64 vs int32), deterministic.
// ---------------------------------------------------------------------------
__global__ void detect_kernel(const int* __restrict__ ec) {
    if (threadIdx.x == 0 && blockIdx.x == 0) {
        int nz = 0;
        #pragma unroll
        for (int i = 1; i < 64; i += 2) nz += (ec[i] != 0);
        g_idx64 = (nz == 0) ? 1 : 0;
    }
}

template <int IS64>
__device__ __forceinline__ int load_idx(const void* p, int i) {
    if (IS64) return (int)__ldg(((const long long*)p) + i);
    return __ldg(((const int*)p) + i);
}

// ---------------------------------------------------------------------------
// W prep: split W (row-major [k][n]) into bf16 hi/lo images B[n][k].
// ---------------------------------------------------------------------------
__global__ void wprep_kernel(const float* __restrict__ W) {
    int i = blockIdx.x * blockDim.x + threadIdx.x;
    if (i >= 128 * 128) return;
    int n = i >> 7, k = i & 127;
    float w = __ldg(W + (size_t)k * 128 + n);
    __nv_bfloat16 hi = __float2bfloat16(w);
    float r = w - __bfloat162float(hi);
    g_whi[n * 128 + k] = __bfloat16_as_ushort(hi);
    g_wlo[n * 128 + k] = __bfloat16_as_ushort(__float2bfloat16(r));
}

// ---------------------------------------------------------------------------
// HMMA GEMM: g_h[M,128] = X[M,128] @ W[128,128]
// 3-pass bf16 split (xhi*whi + xhi*wlo + xlo*whi), fp32 accumulation via
// mma.sync.m16n8k16 (sm_80 baseline -> compiles for plain compute_103).
// CTA tile 128x128, 256 threads = 8 warps (4 m-groups x 2 n-groups).
// ---------------------------------------------------------------------------
#define LDS_STRIDE 136                  // elements; 272B row = 17*16B, conflict-free
#define TILE_BYTES (128 * LDS_STRIDE * 2)
#define SM_XHI 0
#define SM_XLO (SM_XHI + TILE_BYTES)
#define SM_WHI (SM_XLO + TILE_BYTES)
#define SM_WLO (SM_WHI + TILE_BYTES)
#define SM_TOTAL (SM_WLO + TILE_BYTES)

__device__ __forceinline__ void ldsm_x4(uint32_t* r, uint32_t addr) {
    asm volatile("ldmatrix.sync.aligned.m8n8.x4.shared.b16 {%0,%1,%2,%3}, [%4];"
                 : "=r"(r[0]), "=r"(r[1]), "=r"(r[2]), "=r"(r[3]) : "r"(addr));
}
__device__ __forceinline__ void mma_bf16(float* c, const uint32_t* a, const uint32_t* b) {
    asm volatile(
        "mma.sync.aligned.m16n8k16.row.col.f32.bf16.bf16.f32 "
        "{%0,%1,%2,%3}, {%4,%5,%6,%7}, {%8,%9}, {%0,%1,%2,%3};"
        : "+f"(c[0]), "+f"(c[1]), "+f"(c[2]), "+f"(c[3])
        : "r"(a[0]), "r"(a[1]), "r"(a[2]), "r"(a[3]), "r"(b[0]), "r"(b[1]));
}

__global__ __launch_bounds__(256, 1)
void gemm_hmma_kernel(const float* __restrict__ X, int M)
{
    extern __shared__ char smem[];
    const uint32_t sb = smem_u32(smem);
    const int tid = threadIdx.x;
    const int wid = tid >> 5, lane = tid & 31;
    const int m0 = blockIdx.x * 128;

    // ---- stage W hi/lo into smem: thread = (n-row = tid>>1, half = tid&1) ----
    {
        int n = tid >> 1, k0 = (tid & 1) * 64;
        const uint4* shi = (const uint4*)(g_whi + n * 128 + k0);
        const uint4* slo = (const uint4*)(g_wlo + n * 128 + k0);
        uint4* dhi = (uint4*)(smem + SM_WHI + n * (LDS_STRIDE * 2) + k0 * 2);
        uint4* dlo = (uint4*)(smem + SM_WLO + n * (LDS_STRIDE * 2) + k0 * 2);
        #pragma unroll
        for (int j = 0; j < 8; j++) {
            dhi[j] = __ldg(shi + j);
            dlo[j] = __ldg(slo + j);
        }
    }

    // ---- stage X split hi/lo: thread = (row = tid>>1, half = tid&1) ----
    {
        int row = tid >> 1, k0 = (tid & 1) * 64;
        bool valid = (m0 + row) < M;
        const float* xp = X + (size_t)(m0 + row) * 128 + k0;
        char* dhi = smem + SM_XHI + row * (LDS_STRIDE * 2) + k0 * 2;
        char* dlo = smem + SM_XLO + row * (LDS_STRIDE * 2) + k0 * 2;
        #pragma unroll
        for (int j = 0; j < 8; j++) {
            float4 a = make_float4(0, 0, 0, 0), b = a;
            if (valid) {
                a = __ldg((const float4*)(xp + j * 8));
                b = __ldg((const float4*)(xp + j * 8 + 4));
            }
            float f[8] = {a.x, a.y, a.z, a.w, b.x, b.y, b.z, b.w};
            uint32_t hi[8], lo[8];
            #pragma unroll
            for (int q = 0; q < 8; q++) {
                __nv_bfloat16 h = __float2bfloat16(f[q]);
                float r = f[q] - __bfloat162float(h);
                hi[q] = (uint32_t)__bfloat16_as_ushort(h);
                lo[q] = (uint32_t)__bfloat16_as_ushort(__float2bfloat16(r));
            }
            *(uint4*)(dhi + j * 16) = make_uint4(hi[0] | (hi[1] << 16), hi[2] | (hi[3] << 16),
                                                 hi[4] | (hi[5] << 16), hi[6] | (hi[7] << 16));
            *(uint4*)(dlo + j * 16) = make_uint4(lo[0] | (lo[1] << 16), lo[2] | (lo[3] << 16),
                                                 lo[4] | (lo[5] << 16), lo[6] | (lo[7] << 16));
        }
    }
    __syncthreads();

    // ---- warp tile: warp_m in 0..3 (32 rows), warp_n in 0..1 (64 cols) ----
    const int warp_m = wid & 3, warp_n = wid >> 2;
    const int mb = warp_m * 32;
    const int nb = warp_n * 64;

    float acc[2][8][4];
    #pragma unroll
    for (int i = 0; i < 2; i++)
        #pragma unroll
        for (int j = 0; j < 8; j++)
            #pragma unroll
            for (int q = 0; q < 4; q++) acc[i][j][q] = 0.0f;

    // ldmatrix lane addressing
    const int g = lane >> 3, lr = lane & 7;
    // A: row = mb + mt*16 + (g&1)*8 + lr, k = k0 + (g>>1)*8
    // B: row = nb + bt*16 + (g>>1)*8 + lr, k = k0 + (g&1)*8

    #pragma unroll
    for (int kk = 0; kk < 8; kk++) {
        const int k0 = kk * 16;
        uint32_t ahi[2][4], alo[2][4];
        #pragma unroll
        for (int mt = 0; mt < 2; mt++) {
            uint32_t off = (uint32_t)(mb + mt * 16 + (g & 1) * 8 + lr) * (LDS_STRIDE * 2)
                         + (uint32_t)(k0 + (g >> 1) * 8) * 2;
            ldsm_x4(ahi[mt], sb + SM_XHI + off);
            ldsm_x4(alo[mt], sb + SM_XLO + off);
        }
        #pragma unroll
        for (int bt = 0; bt < 4; bt++) {
            uint32_t off = (uint32_t)(nb + bt * 16 + (g >> 1) * 8 + lr) * (LDS_STRIDE * 2)
                         + (uint32_t)(k0 + (g & 1) * 8) * 2;
            uint32_t bhi[4], blo[4];
            ldsm_x4(bhi, sb + SM_WHI + off);   // {b0_t0,b1_t0,b0_t1,b1_t1}
            ldsm_x4(blo, sb + SM_WLO + off);
            #pragma unroll
            for (int mt = 0; mt < 2; mt++)
                #pragma unroll
                for (int nt = 0; nt < 2; nt++) {
                    float* c = acc[mt][bt * 2 + nt];
                    mma_bf16(c, ahi[mt], bhi + nt * 2);
                    mma_bf16(c, ahi[mt], blo + nt * 2);
                    mma_bf16(c, alo[mt], bhi + nt * 2);
                }
        }
    }

    // ---- epilogue: thread t owns (m = mt*16 + t/4 (+8), n = nt*8 + 2*(t%4)) ----
    const int er = lane >> 2, ec2 = (lane & 3) * 2;
    #pragma unroll
    for (int mt = 0; mt < 2; mt++) {
        #pragma unroll
        for (int j = 0; j < 8; j++) {
            int n = nb + j * 8 + ec2;
            int m_lo = m0 + mb + mt * 16 + er;
            int m_hi = m_lo + 8;
            if (m_lo < M)
                *(float2*)(g_h + (size_t)m_lo * 128 + n) =
                    make_float2(acc[mt][j][0], acc[mt][j][1]);
            if (m_hi < M)
                *(float2*)(g_h + (size_t)m_hi * 128 + n) =
                    make_float2(acc[mt][j][2], acc[mt][j][3]);
        }
    }
}

// ---------------------------------------------------------------------------
// CSR row_ptr (guarded by detected index dtype)
// ---------------------------------------------------------------------------
template <int IS64>
__global__ void rowptr_guarded(const void* __restrict__ er, int E, int M) {
    if (g_idx64 != IS64) return;
    int node = blockIdx.x * blockDim.x + threadIdx.x;
    if (node > M) return;
    int lo = 0, hi = E;
    while (lo < hi) {
        int mid = (lo + hi) >> 1;
        if (load_idx<IS64>(er, mid) < node) lo = mid + 1; else hi = mid;
    }
    g_row_ptr[node] = lo;
}

// ---------------------------------------------------------------------------
// SpMM + bias + sigmoid: one warp per row, float4 column slice per lane.
// ---------------------------------------------------------------------------
template <int IS64>
__global__ __launch_bounds__(256) void spmm_guarded(
    const void* __restrict__ ec, const float* __restrict__ ev,
    const float* __restrict__ bias, float* __restrict__ out, int M)
{
    if (g_idx64 != IS64) return;
    int row = blockIdx.x * 8 + (threadIdx.x >> 5);
    if (row >= M) return;
    int lane = threadIdx.x & 31;

    int s = g_row_ptr[row];
    int e = g_row_ptr[row + 1];

    const float4* hp = (const float4*)g_h;
    float4 acc = make_float4(0, 0, 0, 0);

    int i = s;
    for (; i + 4 <= e; i += 4) {
        int c0 = load_idx<IS64>(ec, i + 0);
        int c1 = load_idx<IS64>(ec, i + 1);
        int c2 = load_idx<IS64>(ec, i + 2);
        int c3 = load_idx<IS64>(ec, i + 3);
        float v0 = __ldg(ev + i + 0);
        float v1 = __ldg(ev + i + 1);
        float v2 = __ldg(ev + i + 2);
        float v3 = __ldg(ev + i + 3);
        float4 h0 = hp[(size_t)c0 * 32 + lane];
        float4 h1 = hp[(size_t)c1 * 32 + lane];
        float4 h2 = hp[(size_t)c2 * 32 + lane];
        float4 h3 = hp[(size_t)c3 * 32 + lane];
        acc.x = fmaf(v0, h0.x, acc.x); acc.y = fmaf(v0, h0.y, acc.y);
        acc.z = fmaf(v0, h0.z, acc.z); acc.w = fmaf(v0, h0.w, acc.w);
        acc.x = fmaf(v1, h1.x, acc.x); acc.y = fmaf(v1, h1.y, acc.y);
        acc.z = fmaf(v1, h1.z, acc.z); acc.w = fmaf(v1, h1.w, acc.w);
        acc.x = fmaf(v2, h2.x, acc.x); acc.y = fmaf(v2, h2.y, acc.y);
        acc.z = fmaf(v2, h2.z, acc.z); acc.w = fmaf(v2, h2.w, acc.w);
        acc.x = fmaf(v3, h3.x, acc.x); acc.y = fmaf(v3, h3.y, acc.y);
        acc.z = fmaf(v3, h3.z, acc.z); acc.w = fmaf(v3, h3.w, acc.w);
    }
    for (; i < e; i++) {
        int c = load_idx<IS64>(ec, i);
        float v = __ldg(ev + i);
        float4 h = hp[(size_t)c * 32 + lane];
        acc.x = fmaf(v, h.x, acc.x); acc.y = fmaf(v, h.y, acc.y);
        acc.z = fmaf(v, h.z, acc.z); acc.w = fmaf(v, h.w, acc.w);
    }

    float4 b = __ldg(((const float4*)bias) + lane);
    float4 r;
    r.x = 1.0f / (1.0f + __expf(-(acc.x + b.x)));
    r.y = 1.0f / (1.0f + __expf(-(acc.y + b.y)));
    r.z = 1.0f / (1.0f + __expf(-(acc.z + b.z)));
    r.w = 1.0f / (1.0f + __expf(-(acc.w + b.w)));
    ((float4*)out)[(size_t)row * 32 + lane] = r;
}

// ---------------------------------------------------------------------------
// Launch. Inputs: X, edge_row, edge_col, edge_val, weight, bias
// ---------------------------------------------------------------------------
extern "C" void kernel_launch(void* const* d_in, const int* in_sizes, int n_in,
                              void* d_out, int out_size) {
    const float* X    = (const float*)d_in[0];
    const void*  er   = d_in[1];
    const void*  ec   = d_in[2];
    const float* ev   = (const float*)d_in[3];
    const float* W    = (const float*)d_in[4];
    const float* bias = (const float*)d_in[5];
    float* out = (float*)d_out;

    int M = in_sizes[0] / UNITS;     // 100000
    int E = in_sizes[2];             // 1600000

    static int smem_set = 0;
    if (!smem_set) {
        cudaFuncSetAttribute(gemm_hmma_kernel,
                             cudaFuncAttributeMaxDynamicSharedMemorySize, SM_TOTAL);
        smem_set = 1;
    }

    detect_kernel<<<1, 32>>>((const int*)ec);
    wprep_kernel<<<64, 256>>>(W);
    gemm_hmma_kernel<<<(M + 127) / 128, 256, SM_TOTAL>>>(X, M);

    rowptr_guarded<0><<<(M + 256) / 256, 256>>>(er, E, M);
    rowptr_guarded<1><<<(M + 256) / 256, 256>>>(er, E, M);

    int spmm_blocks = (M + 7) / 8;
    spmm_guarded<0><<<spmm_blocks, 256>>>(ec, ev, bias, out, M);
    spmm_guarded<1><<<spmm_blocks, 256>>>(ec, ev, bias, out, M);
}

// round 8
// speedup vs baseline: 3.0271x; 1.0913x over previous
#include <cuda_runtime.h>
#include <cuda_bf16.h>
#include <cstdint>

#define MAX_NODES 100000
#define UNITS 128

// ---------------------------------------------------------------------------
// Scratch (no cudaMalloc allowed)
// ---------------------------------------------------------------------------
__device__ __align__(16) float g_h[(size_t)MAX_NODES * UNITS];  // 51.2 MB
__device__ int   g_row_ptr[MAX_NODES + 1];
__device__ int   g_idx64;
// W split into bf16 hi/lo, stored as B[n][k] = W[k][n], row-major [128][128]
__device__ __align__(16) unsigned short g_whi[128 * 128];
__device__ __align__(16) unsigned short g_wlo[128 * 128];

__device__ __forceinline__ uint32_t smem_u32(const void* p) {
    uint32_t a;
    asm("{ .reg .u64 t; cvta.to.shared.u64 t, %1; cvt.u32.u64 %0, t; }"
        : "=r"(a) : "l"(p));
    return a;
}

template <int IS64>
__device__ __forceinline__ int load_idx(const void* p, int i) {
    if (IS64) return (int)__ldg(((const long long*)p) + i);
    return __ldg(((const int*)p) + i);
}

// ---------------------------------------------------------------------------
// Fused prep: W split into bf16 hi/lo images B[n][k]  +  index-dtype probe.
// 64 blocks x 256 threads cover 16384 W elements; block 0 lane 0 also detects.
// ---------------------------------------------------------------------------
__global__ void prep_kernel(const float* __restrict__ W, const int* __restrict__ ec) {
    if (blockIdx.x == 0 && threadIdx.x == 0) {
        int nz = 0;
        #pragma unroll
        for (int i = 1; i < 64; i += 2) nz += (ec[i] != 0);
        g_idx64 = (nz == 0) ? 1 : 0;
    }
    int i = blockIdx.x * blockDim.x + threadIdx.x;
    if (i >= 128 * 128) return;
    int n = i >> 7, k = i & 127;
    float w = __ldg(W + (size_t)k * 128 + n);
    __nv_bfloat16 hi = __float2bfloat16(w);
    float r = w - __bfloat162float(hi);
    g_whi[n * 128 + k] = __bfloat16_as_ushort(hi);
    g_wlo[n * 128 + k] = __bfloat16_as_ushort(__float2bfloat16(r));
}

// ---------------------------------------------------------------------------
// CSR row_ptr via edge-difference scatter (one pass, coalesced).
// row_ptr[r] = i  for all r in (er[i-1], er[i]];  row_ptr[0..er[0]] = 0;
// row_ptr[r] = E  for r > er[E-1].
// ---------------------------------------------------------------------------
template <int IS64>
__device__ __forceinline__ void rowptr_body(const void* er, int E, int M) {
    int i = blockIdx.x * blockDim.x + threadIdx.x;
    if (i > E) return;
    if (i == E) {
        int last = load_idx<IS64>(er, E - 1);
        for (int r = last + 1; r <= M; r++) g_row_ptr[r] = E;
        return;
    }
    int r1 = load_idx<IS64>(er, i);
    int r0 = (i == 0) ? -1 : load_idx<IS64>(er, i - 1);
    for (int r = r0 + 1; r <= r1; r++) g_row_ptr[r] = i;
}

__global__ void rowptr_kernel(const void* __restrict__ er, int E, int M) {
    if (g_idx64) rowptr_body<1>(er, E, M);
    else         rowptr_body<0>(er, E, M);
}

// ---------------------------------------------------------------------------
// HMMA GEMM: g_h[M,128] = X[M,128] @ W[128,128]
// 3-pass bf16 split (xhi*whi + xhi*wlo + xlo*whi), fp32 accumulation via
// mma.sync.m16n8k16. CTA tile 128x128, 256 threads = 8 warps (4m x 2n).
// ---------------------------------------------------------------------------
#define LDS_STRIDE 136                  // elements; 272B row = 17*16B, conflict-free
#define TILE_BYTES (128 * LDS_STRIDE * 2)
#define SM_XHI 0
#define SM_XLO (SM_XHI + TILE_BYTES)
#define SM_WHI (SM_XLO + TILE_BYTES)
#define SM_WLO (SM_WHI + TILE_BYTES)
#define SM_TOTAL (SM_WLO + TILE_BYTES)

__device__ __forceinline__ void ldsm_x4(uint32_t* r, uint32_t addr) {
    asm volatile("ldmatrix.sync.aligned.m8n8.x4.shared.b16 {%0,%1,%2,%3}, [%4];"
                 : "=r"(r[0]), "=r"(r[1]), "=r"(r[2]), "=r"(r[3]) : "r"(addr));
}
__device__ __forceinline__ void mma_bf16(float* c, const uint32_t* a, const uint32_t* b) {
    asm volatile(
        "mma.sync.aligned.m16n8k16.row.col.f32.bf16.bf16.f32 "
        "{%0,%1,%2,%3}, {%4,%5,%6,%7}, {%8,%9}, {%0,%1,%2,%3};"
        : "+f"(c[0]), "+f"(c[1]), "+f"(c[2]), "+f"(c[3])
        : "r"(a[0]), "r"(a[1]), "r"(a[2]), "r"(a[3]), "r"(b[0]), "r"(b[1]));
}

__global__ __launch_bounds__(256, 1)
void gemm_hmma_kernel(const float* __restrict__ X, int M)
{
    extern __shared__ char smem[];
    const uint32_t sb = smem_u32(smem);
    const int tid = threadIdx.x;
    const int wid = tid >> 5, lane = tid & 31;
    const int m0 = blockIdx.x * 128;

    // ---- stage W hi/lo into smem ----
    {
        int n = tid >> 1, k0 = (tid & 1) * 64;
        const uint4* shi = (const uint4*)(g_whi + n * 128 + k0);
        const uint4* slo = (const uint4*)(g_wlo + n * 128 + k0);
        uint4* dhi = (uint4*)(smem + SM_WHI + n * (LDS_STRIDE * 2) + k0 * 2);
        uint4* dlo = (uint4*)(smem + SM_WLO + n * (LDS_STRIDE * 2) + k0 * 2);
        #pragma unroll
        for (int j = 0; j < 8; j++) {
            dhi[j] = __ldg(shi + j);
            dlo[j] = __ldg(slo + j);
        }
    }

    // ---- stage X split hi/lo ----
    {
        int row = tid >> 1, k0 = (tid & 1) * 64;
        bool valid = (m0 + row) < M;
        const float* xp = X + (size_t)(m0 + row) * 128 + k0;
        char* dhi = smem + SM_XHI + row * (LDS_STRIDE * 2) + k0 * 2;
        char* dlo = smem + SM_XLO + row * (LDS_STRIDE * 2) + k0 * 2;
        #pragma unroll
        for (int j = 0; j < 8; j++) {
            float4 a = make_float4(0, 0, 0, 0), b = a;
            if (valid) {
                a = __ldg((const float4*)(xp + j * 8));
                b = __ldg((const float4*)(xp + j * 8 + 4));
            }
            float f[8] = {a.x, a.y, a.z, a.w, b.x, b.y, b.z, b.w};
            uint32_t hi[8], lo[8];
            #pragma unroll
            for (int q = 0; q < 8; q++) {
                __nv_bfloat16 h = __float2bfloat16(f[q]);
                float r = f[q] - __bfloat162float(h);
                hi[q] = (uint32_t)__bfloat16_as_ushort(h);
                lo[q] = (uint32_t)__bfloat16_as_ushort(__float2bfloat16(r));
            }
            *(uint4*)(dhi + j * 16) = make_uint4(hi[0] | (hi[1] << 16), hi[2] | (hi[3] << 16),
                                                 hi[4] | (hi[5] << 16), hi[6] | (hi[7] << 16));
            *(uint4*)(dlo + j * 16) = make_uint4(lo[0] | (lo[1] << 16), lo[2] | (lo[3] << 16),
                                                 lo[4] | (lo[5] << 16), lo[6] | (lo[7] << 16));
        }
    }
    __syncthreads();

    const int warp_m = wid & 3, warp_n = wid >> 2;
    const int mb = warp_m * 32;
    const int nb = warp_n * 64;

    float acc[2][8][4];
    #pragma unroll
    for (int i = 0; i < 2; i++)
        #pragma unroll
        for (int j = 0; j < 8; j++)
            #pragma unroll
            for (int q = 0; q < 4; q++) acc[i][j][q] = 0.0f;

    const int g = lane >> 3, lr = lane & 7;

    #pragma unroll
    for (int kk = 0; kk < 8; kk++) {
        const int k0 = kk * 16;
        uint32_t ahi[2][4], alo[2][4];
        #pragma unroll
        for (int mt = 0; mt < 2; mt++) {
            uint32_t off = (uint32_t)(mb + mt * 16 + (g & 1) * 8 + lr) * (LDS_STRIDE * 2)
                         + (uint32_t)(k0 + (g >> 1) * 8) * 2;
            ldsm_x4(ahi[mt], sb + SM_XHI + off);
            ldsm_x4(alo[mt], sb + SM_XLO + off);
        }
        #pragma unroll
        for (int bt = 0; bt < 4; bt++) {
            uint32_t off = (uint32_t)(nb + bt * 16 + (g >> 1) * 8 + lr) * (LDS_STRIDE * 2)
                         + (uint32_t)(k0 + (g & 1) * 8) * 2;
            uint32_t bhi[4], blo[4];
            ldsm_x4(bhi, sb + SM_WHI + off);
            ldsm_x4(blo, sb + SM_WLO + off);
            #pragma unroll
            for (int mt = 0; mt < 2; mt++)
                #pragma unroll
                for (int nt = 0; nt < 2; nt++) {
                    float* c = acc[mt][bt * 2 + nt];
                    mma_bf16(c, ahi[mt], bhi + nt * 2);
                    mma_bf16(c, ahi[mt], blo + nt * 2);
                    mma_bf16(c, alo[mt], bhi + nt * 2);
                }
        }
    }

    const int er = lane >> 2, ec2 = (lane & 3) * 2;
    #pragma unroll
    for (int mt = 0; mt < 2; mt++) {
        #pragma unroll
        for (int j = 0; j < 8; j++) {
            int n = nb + j * 8 + ec2;
            int m_lo = m0 + mb + mt * 16 + er;
            int m_hi = m_lo + 8;
            if (m_lo < M)
                *(float2*)(g_h + (size_t)m_lo * 128 + n) =
                    make_float2(acc[mt][j][0], acc[mt][j][1]);
            if (m_hi < M)
                *(float2*)(g_h + (size_t)m_hi * 128 + n) =
                    make_float2(acc[mt][j][2], acc[mt][j][3]);
        }
    }
}

// ---------------------------------------------------------------------------
// SpMM + bias + sigmoid: one warp per row, float4 column slice per lane.
// 8-edge unroll (MLP=8), then 4/1 remainder. Uniform runtime dtype branch.
// ---------------------------------------------------------------------------
template <int IS64>
__device__ __forceinline__ void spmm_body(
    const void* ec, const float* ev, const float* bias, float* out, int M)
{
    int row = blockIdx.x * 8 + (threadIdx.x >> 5);
    if (row >= M) return;
    int lane = threadIdx.x & 31;

    int s = __ldg(&g_row_ptr[row]);
    int e = __ldg(&g_row_ptr[row + 1]);

    const float4* hp = (const float4*)g_h;
    float4 acc = make_float4(0, 0, 0, 0);

    int i = s;
    for (; i + 8 <= e; i += 8) {
        int   c[8];
        float v[8];
        #pragma unroll
        for (int q = 0; q < 8; q++) {
            c[q] = load_idx<IS64>(ec, i + q);
            v[q] = __ldg(ev + i + q);
        }
        float4 h[8];
        #pragma unroll
        for (int q = 0; q < 8; q++) h[q] = hp[(size_t)c[q] * 32 + lane];
        #pragma unroll
        for (int q = 0; q < 8; q++) {
            acc.x = fmaf(v[q], h[q].x, acc.x);
            acc.y = fmaf(v[q], h[q].y, acc.y);
            acc.z = fmaf(v[q], h[q].z, acc.z);
            acc.w = fmaf(v[q], h[q].w, acc.w);
        }
    }
    if (i + 4 <= e) {
        int   c[4];
        float v[4];
        #pragma unroll
        for (int q = 0; q < 4; q++) {
            c[q] = load_idx<IS64>(ec, i + q);
            v[q] = __ldg(ev + i + q);
        }
        float4 h[4];
        #pragma unroll
        for (int q = 0; q < 4; q++) h[q] = hp[(size_t)c[q] * 32 + lane];
        #pragma unroll
        for (int q = 0; q < 4; q++) {
            acc.x = fmaf(v[q], h[q].x, acc.x);
            acc.y = fmaf(v[q], h[q].y, acc.y);
            acc.z = fmaf(v[q], h[q].z, acc.z);
            acc.w = fmaf(v[q], h[q].w, acc.w);
        }
        i += 4;
    }
    for (; i < e; i++) {
        int c0 = load_idx<IS64>(ec, i);
        float v0 = __ldg(ev + i);
        float4 h0 = hp[(size_t)c0 * 32 + lane];
        acc.x = fmaf(v0, h0.x, acc.x); acc.y = fmaf(v0, h0.y, acc.y);
        acc.z = fmaf(v0, h0.z, acc.z); acc.w = fmaf(v0, h0.w, acc.w);
    }

    float4 b = __ldg(((const float4*)bias) + lane);
    float4 r;
    r.x = 1.0f / (1.0f + __expf(-(acc.x + b.x)));
    r.y = 1.0f / (1.0f + __expf(-(acc.y + b.y)));
    r.z = 1.0f / (1.0f + __expf(-(acc.z + b.z)));
    r.w = 1.0f / (1.0f + __expf(-(acc.w + b.w)));
    ((float4*)out)[(size_t)row * 32 + lane] = r;
}

__global__ __launch_bounds__(256) void spmm_kernel(
    const void* __restrict__ ec, const float* __restrict__ ev,
    const float* __restrict__ bias, float* __restrict__ out, int M)
{
    if (g_idx64) spmm_body<1>(ec, ev, bias, out, M);
    else         spmm_body<0>(ec, ev, bias, out, M);
}

// ---------------------------------------------------------------------------
// Launch. Inputs: X, edge_row, edge_col, edge_val, weight, bias
// ---------------------------------------------------------------------------
extern "C" void kernel_launch(void* const* d_in, const int* in_sizes, int n_in,
                              void* d_out, int out_size) {
    const float* X    = (const float*)d_in[0];
    const void*  er   = d_in[1];
    const void*  ec   = d_in[2];
    const float* ev   = (const float*)d_in[3];
    const float* W    = (const float*)d_in[4];
    const float* bias = (const float*)d_in[5];
    float* out = (float*)d_out;

    int M = in_sizes[0] / UNITS;     // 100000
    int E = in_sizes[2];             // 1600000

    static int smem_set = 0;
    if (!smem_set) {
        cudaFuncSetAttribute(gemm_hmma_kernel,
                             cudaFuncAttributeMaxDynamicSharedMemorySize, SM_TOTAL);
        smem_set = 1;
    }

    prep_kernel<<<64, 256>>>(W, (const int*)ec);          // W split + dtype detect
    rowptr_kernel<<<(E + 256) / 256, 256>>>(er, E, M);    // edge-diff scatter
    gemm_hmma_kernel<<<(M + 127) / 128, 256, SM_TOTAL>>>(X, M);
    spmm_kernel<<<(M + 7) / 8, 256>>>(ec, ev, bias, out, M);
}